// round 12
// baseline (speedup 1.0000x reference)
#include <cuda_runtime.h>
#include <cuda_bf16.h>
#include <math.h>

// Problem constants (match reference)
#define NN 50000
#define EG 800000
#define EE (EG + NN)   // edges + self loops = 850000
#define FD 128
#define PP 200000
#define ALPHA 0.1f

// ---------------------------------------------------------------------------
// Device scratch (no cudaMalloc allowed)
// ---------------------------------------------------------------------------
__device__ int   g_cnt[NN];
__device__ int   g_rowptr[NN + 1];
__device__ int   g_cursor[NN];
__device__ float g_dinv[NN];
__device__ int   g_col[EE];
__device__ float g_val[EE];
__device__ float g_H0[(size_t)NN * FD];
__device__ float g_Ha[(size_t)NN * FD];
__device__ float g_Hb[(size_t)NN * FD];

// ---------------------------------------------------------------------------
// 1. init: cnt[v] = 1 (self loop)
// ---------------------------------------------------------------------------
__global__ void k_init() {
    int v = blockIdx.x * blockDim.x + threadIdx.x;
    if (v < NN) g_cnt[v] = 1;
}

// 2. histogram of dst
__global__ void k_hist(const int* __restrict__ ei) {
    int e = blockIdx.x * blockDim.x + threadIdx.x;
    if (e < EG) atomicAdd(&g_cnt[ei[EG + e]], 1);
}

// 3. single-block exclusive scan: g_cnt -> g_rowptr  (n = NN)
__global__ void k_scan() {
    __shared__ int sums[1024];
    const int n = NN;
    const int chunk = (n + 1023) / 1024;   // 49
    int tid = threadIdx.x;
    int beg = tid * chunk;
    int end = min(beg + chunk, n);
    int s = 0;
    for (int i = beg; i < end; i++) s += g_cnt[i];
    sums[tid] = s;
    __syncthreads();
    // Hillis-Steele inclusive scan
    for (int off = 1; off < 1024; off <<= 1) {
        int t = 0;
        if (tid >= off) t = sums[tid - off];
        __syncthreads();
        if (tid >= off) sums[tid] += t;
        __syncthreads();
    }
    int base = (tid > 0) ? sums[tid - 1] : 0;
    int run = base;
    for (int i = beg; i < end; i++) {
        g_rowptr[i] = run;
        run += g_cnt[i];
    }
    if (tid == 1023) g_rowptr[n] = sums[1023];
}

// 4. dinv + cursor init
__global__ void k_prep() {
    int v = blockIdx.x * blockDim.x + threadIdx.x;
    if (v < NN) {
        g_dinv[v] = rsqrtf((float)g_cnt[v]);   // deg >= 1 (self loop)
        g_cursor[v] = g_rowptr[v];
    }
}

// 5. fill CSR (edges + self loops)
__global__ void k_fill(const int* __restrict__ ei) {
    int i = blockIdx.x * blockDim.x + threadIdx.x;
    if (i >= EE) return;
    int s, d;
    if (i < EG) { s = ei[i]; d = ei[EG + i]; }
    else        { s = d = i - EG; }
    int pos = atomicAdd(&g_cursor[d], 1);
    g_col[pos] = s;
    g_val[pos] = g_dinv[s] * g_dinv[d];
}

// ---------------------------------------------------------------------------
// GEMM:  Y[N,128] = (relu?)X[N,128] @ W[128,128]^T + b
// W row-major: W[f*128+d].  WT staged in smem, 8 rows per block iteration.
// ---------------------------------------------------------------------------
__global__ void k_gemm(const float* __restrict__ X, const float* __restrict__ W,
                       const float* __restrict__ bias, float* __restrict__ Y,
                       int relu_in) {
    extern __shared__ float sm[];
    float* WT = sm;               // [128*128]  WT[d*128+f]
    float* xs = sm + 128 * 128;   // [128][8]
    int tid = threadIdx.x;        // blockDim = 128

    for (int i = tid; i < 128 * 128; i += 128) {
        int f = i >> 7, d = i & 127;
        WT[(d << 7) | f] = W[i];
    }
    float bv = bias[tid];
    __syncthreads();

    for (int vb = blockIdx.x * 8; vb < NN; vb += gridDim.x * 8) {
#pragma unroll
        for (int r = 0; r < 8; r++) {
            float xv = X[(size_t)(vb + r) * 128 + tid];
            if (relu_in) xv = fmaxf(xv, 0.0f);
            xs[tid * 8 + r] = xv;
        }
        __syncthreads();
        float acc[8];
#pragma unroll
        for (int r = 0; r < 8; r++) acc[r] = bv;
#pragma unroll 16
        for (int d = 0; d < 128; d++) {
            float w = WT[(d << 7) + tid];
            float4 xlo = *(const float4*)(xs + d * 8);
            float4 xhi = *(const float4*)(xs + d * 8 + 4);
            acc[0] += xlo.x * w; acc[1] += xlo.y * w;
            acc[2] += xlo.z * w; acc[3] += xlo.w * w;
            acc[4] += xhi.x * w; acc[5] += xhi.y * w;
            acc[6] += xhi.z * w; acc[7] += xhi.w * w;
        }
#pragma unroll
        for (int r = 0; r < 8; r++)
            Y[(size_t)(vb + r) * 128 + tid] = acc[r];
        __syncthreads();
    }
}

// ---------------------------------------------------------------------------
// APPNP propagate step:  hout[v] = 0.9 * sum_e val[e]*hin[col[e]] + 0.1*x0[v]
// warp per node, float4 per lane (128 feats), 4-edge unroll for MLP.
// ---------------------------------------------------------------------------
__global__ void k_prop(const float* __restrict__ hin, const float* __restrict__ x0,
                       float* __restrict__ hout) {
    int gw = (blockIdx.x * blockDim.x + threadIdx.x) >> 5;
    int lane = threadIdx.x & 31;
    if (gw >= NN) return;

    int beg = g_rowptr[gw];
    int end = g_rowptr[gw + 1];
    const float4* hin4 = (const float4*)hin;

    float ax = 0.f, ay = 0.f, az = 0.f, aw = 0.f;
    int e = beg;
    for (; e + 4 <= end; e += 4) {
        int s0 = g_col[e],     s1 = g_col[e + 1];
        int s2 = g_col[e + 2], s3 = g_col[e + 3];
        float w0 = g_val[e],     w1 = g_val[e + 1];
        float w2 = g_val[e + 2], w3 = g_val[e + 3];
        float4 v0 = hin4[(size_t)s0 * 32 + lane];
        float4 v1 = hin4[(size_t)s1 * 32 + lane];
        float4 v2 = hin4[(size_t)s2 * 32 + lane];
        float4 v3 = hin4[(size_t)s3 * 32 + lane];
        ax += w0 * v0.x + w1 * v1.x + w2 * v2.x + w3 * v3.x;
        ay += w0 * v0.y + w1 * v1.y + w2 * v2.y + w3 * v3.y;
        az += w0 * v0.z + w1 * v1.z + w2 * v2.z + w3 * v3.z;
        aw += w0 * v0.w + w1 * v1.w + w2 * v2.w + w3 * v3.w;
    }
    for (; e < end; e++) {
        int s = g_col[e];
        float w = g_val[e];
        float4 v = hin4[(size_t)s * 32 + lane];
        ax += w * v.x; ay += w * v.y; az += w * v.z; aw += w * v.w;
    }
    float4 xv = ((const float4*)x0)[(size_t)gw * 32 + lane];
    float4 o;
    o.x = (1.0f - ALPHA) * ax + ALPHA * xv.x;
    o.y = (1.0f - ALPHA) * ay + ALPHA * xv.y;
    o.z = (1.0f - ALPHA) * az + ALPHA * xv.z;
    o.w = (1.0f - ALPHA) * aw + ALPHA * xv.w;
    ((float4*)hout)[(size_t)gw * 32 + lane] = o;
}

// ---------------------------------------------------------------------------
// Link layer: warp per pair.
// out[p] = log_softmax( [relu(h[i0]), relu(h[i1])] @ W3^T + b3 )
// W3 row-major [2, 256].
// ---------------------------------------------------------------------------
__global__ void k_link(const float* __restrict__ h, const int* __restrict__ idx,
                       const float* __restrict__ W3, const float* __restrict__ b3,
                       float* __restrict__ out) {
    int gw = (blockIdx.x * blockDim.x + threadIdx.x) >> 5;
    int lane = threadIdx.x & 31;
    if (gw >= PP) return;

    // per-lane weight slices (lane handles features 4*lane..4*lane+3)
    float4 w00 = *(const float4*)(W3 + 4 * lane);          // row0, first half
    float4 w01 = *(const float4*)(W3 + 128 + 4 * lane);    // row0, second half
    float4 w10 = *(const float4*)(W3 + 256 + 4 * lane);    // row1, first half
    float4 w11 = *(const float4*)(W3 + 256 + 128 + 4 * lane);

    int i0 = idx[2 * gw];
    int i1 = idx[2 * gw + 1];
    float4 a = ((const float4*)h)[(size_t)i0 * 32 + lane];
    float4 b = ((const float4*)h)[(size_t)i1 * 32 + lane];
    a.x = fmaxf(a.x, 0.f); a.y = fmaxf(a.y, 0.f);
    a.z = fmaxf(a.z, 0.f); a.w = fmaxf(a.w, 0.f);
    b.x = fmaxf(b.x, 0.f); b.y = fmaxf(b.y, 0.f);
    b.z = fmaxf(b.z, 0.f); b.w = fmaxf(b.w, 0.f);

    float l0 = a.x * w00.x + a.y * w00.y + a.z * w00.z + a.w * w00.w
             + b.x * w01.x + b.y * w01.y + b.z * w01.z + b.w * w01.w;
    float l1 = a.x * w10.x + a.y * w10.y + a.z * w10.z + a.w * w10.w
             + b.x * w11.x + b.y * w11.y + b.z * w11.z + b.w * w11.w;

#pragma unroll
    for (int off = 16; off; off >>= 1) {
        l0 += __shfl_xor_sync(0xffffffffu, l0, off);
        l1 += __shfl_xor_sync(0xffffffffu, l1, off);
    }
    if (lane == 0) {
        l0 += b3[0];
        l1 += b3[1];
        float m = fmaxf(l0, l1);
        float lse = m + logf(expf(l0 - m) + expf(l1 - m));
        out[2 * gw]     = l0 - lse;
        out[2 * gw + 1] = l1 - lse;
    }
}

// ---------------------------------------------------------------------------
// Launch
// ---------------------------------------------------------------------------
extern "C" void kernel_launch(void* const* d_in, const int* in_sizes, int n_in,
                              void* d_out, int out_size) {
    const float* x     = (const float*)d_in[0];
    const int*   ei    = (const int*)d_in[1];
    const int*   index = (const int*)d_in[2];
    const float* W1    = (const float*)d_in[3];
    const float* b1    = (const float*)d_in[4];
    const float* W2    = (const float*)d_in[5];
    const float* b2    = (const float*)d_in[6];
    const float* W3    = (const float*)d_in[7];
    const float* b3    = (const float*)d_in[8];
    float* out = (float*)d_out;

    float *H0, *Ha, *Hb;
    cudaGetSymbolAddress((void**)&H0, g_H0);
    cudaGetSymbolAddress((void**)&Ha, g_Ha);
    cudaGetSymbolAddress((void**)&Hb, g_Hb);

    const int gemm_smem = (128 * 128 + 128 * 8) * (int)sizeof(float);  // 69632
    cudaFuncSetAttribute(k_gemm, cudaFuncAttributeMaxDynamicSharedMemorySize,
                         gemm_smem);

    // ---- graph normalization / CSR build ----
    k_init<<<(NN + 255) / 256, 256>>>();
    k_hist<<<(EG + 255) / 256, 256>>>(ei);
    k_scan<<<1, 1024>>>();
    k_prep<<<(NN + 255) / 256, 256>>>();
    k_fill<<<(EE + 255) / 256, 256>>>(ei);

    const int prop_blocks = (NN * 32 + 255) / 256;   // 6250
    const int gemm_blocks = 444;                     // 3 blocks/SM resident

    // ---- layer 1: H0 = x @ W1^T + b1 ; 10x APPNP ----
    k_gemm<<<gemm_blocks, 128, gemm_smem>>>(x, W1, b1, H0, 0);
    {
        const float* cur = H0;
        float* bufs[2] = {Ha, Hb};
        for (int k = 0; k < 10; k++) {
            float* o = bufs[k & 1];
            k_prop<<<prop_blocks, 256>>>(cur, H0, o);
            cur = o;
        }
        // cur == Hb
    }

    // ---- layer 2: H0 = relu(Hb) @ W2^T + b2 ; 10x APPNP ----
    k_gemm<<<gemm_blocks, 128, gemm_smem>>>(Hb, W2, b2, H0, 1);
    {
        const float* cur = H0;
        float* bufs[2] = {Ha, Hb};
        for (int k = 0; k < 10; k++) {
            float* o = bufs[k & 1];
            k_prop<<<prop_blocks, 256>>>(cur, H0, o);
            cur = o;
        }
        // cur == Hb
    }

    // ---- link prediction head ----
    k_link<<<(PP * 32 + 255) / 256, 256>>>(Hb, index, W3, b3, out);
}

// round 13
// speedup vs baseline: 1.2004x; 1.2004x over previous
#include <cuda_runtime.h>
#include <cuda_fp16.h>
#include <cuda_bf16.h>
#include <math.h>

// Problem constants (match reference)
#define NN 50000
#define EG 800000
#define EE (EG + NN)   // edges + self loops = 850000
#define FD 128
#define PP 200000
#define ALPHA 0.1f

// ---------------------------------------------------------------------------
// Device scratch (no cudaMalloc allowed)
// ---------------------------------------------------------------------------
__device__ int   g_cnt[NN];
__device__ int   g_rowptr[NN + 1];
__device__ int   g_cursor[NN];
__device__ float g_dinv[NN];
__device__ uint2 g_meta[EE];                     // (col, weight-bits)
__device__ float g_Hf[(size_t)NN * FD];          // fp32 GEMM output / x0 anchor
__device__ float g_Hg[(size_t)NN * FD];          // fp32 final-prop output
__device__ uint2 g_h1[(size_t)NN * FD / 4];      // half ping buffer (4 halves / uint2)
__device__ uint2 g_h2[(size_t)NN * FD / 4];      // half pong buffer

// ---------------------------------------------------------------------------
// CSR build
// ---------------------------------------------------------------------------
__global__ void k_init() {
    int v = blockIdx.x * blockDim.x + threadIdx.x;
    if (v < NN) g_cnt[v] = 1;                    // self loop
}

__global__ void k_hist(const int* __restrict__ ei) {
    int e = blockIdx.x * blockDim.x + threadIdx.x;
    if (e < EG) atomicAdd(&g_cnt[ei[EG + e]], 1);
}

__global__ void k_scan() {
    __shared__ int sums[1024];
    const int n = NN;
    const int chunk = (n + 1023) / 1024;
    int tid = threadIdx.x;
    int beg = tid * chunk;
    int end = min(beg + chunk, n);
    int s = 0;
    for (int i = beg; i < end; i++) s += g_cnt[i];
    sums[tid] = s;
    __syncthreads();
    for (int off = 1; off < 1024; off <<= 1) {
        int t = 0;
        if (tid >= off) t = sums[tid - off];
        __syncthreads();
        if (tid >= off) sums[tid] += t;
        __syncthreads();
    }
    int base = (tid > 0) ? sums[tid - 1] : 0;
    int run = base;
    for (int i = beg; i < end; i++) {
        g_rowptr[i] = run;
        run += g_cnt[i];
    }
    if (tid == 1023) g_rowptr[n] = sums[1023];
}

__global__ void k_prep() {
    int v = blockIdx.x * blockDim.x + threadIdx.x;
    if (v < NN) {
        g_dinv[v] = rsqrtf((float)g_cnt[v]);
        g_cursor[v] = g_rowptr[v];
    }
}

__global__ void k_fill(const int* __restrict__ ei) {
    int i = blockIdx.x * blockDim.x + threadIdx.x;
    if (i >= EE) return;
    int s, d;
    if (i < EG) { s = ei[i]; d = ei[EG + i]; }
    else        { s = d = i - EG; }
    int pos = atomicAdd(&g_cursor[d], 1);
    float w = g_dinv[s] * g_dinv[d];
    g_meta[pos] = make_uint2((unsigned)s, __float_as_uint(w));
}

// ---------------------------------------------------------------------------
// GEMM:  Yf/Yh[N,128] = (relu?)X[N,128] @ W[128,128]^T + b
// Writes BOTH fp32 (teleport anchor / downstream) and fp16 (gather source).
// ---------------------------------------------------------------------------
__global__ void k_gemm(const float* __restrict__ X, const float* __restrict__ W,
                       const float* __restrict__ bias,
                       float* __restrict__ Yf, __half* __restrict__ Yh,
                       int relu_in) {
    extern __shared__ float sm[];
    float* WT = sm;               // [128*128]  WT[d*128+f]
    float* xs = sm + 128 * 128;   // [128][8]
    int tid = threadIdx.x;        // blockDim = 128

    for (int i = tid; i < 128 * 128; i += 128) {
        int f = i >> 7, d = i & 127;
        WT[(d << 7) | f] = W[i];
    }
    float bv = bias[tid];
    __syncthreads();

    for (int vb = blockIdx.x * 8; vb < NN; vb += gridDim.x * 8) {
#pragma unroll
        for (int r = 0; r < 8; r++) {
            float xv = X[(size_t)(vb + r) * 128 + tid];
            if (relu_in) xv = fmaxf(xv, 0.0f);
            xs[tid * 8 + r] = xv;
        }
        __syncthreads();
        float acc[8];
#pragma unroll
        for (int r = 0; r < 8; r++) acc[r] = bv;
#pragma unroll 16
        for (int d = 0; d < 128; d++) {
            float w = WT[(d << 7) + tid];
            float4 xlo = *(const float4*)(xs + d * 8);
            float4 xhi = *(const float4*)(xs + d * 8 + 4);
            acc[0] += xlo.x * w; acc[1] += xlo.y * w;
            acc[2] += xlo.z * w; acc[3] += xlo.w * w;
            acc[4] += xhi.x * w; acc[5] += xhi.y * w;
            acc[6] += xhi.z * w; acc[7] += xhi.w * w;
        }
#pragma unroll
        for (int r = 0; r < 8; r++) {
            Yf[(size_t)(vb + r) * 128 + tid] = acc[r];
            Yh[(size_t)(vb + r) * 128 + tid] = __float2half_rn(acc[r]);
        }
        __syncthreads();
    }
}

// ---------------------------------------------------------------------------
// APPNP propagate step (fp16 gather, fp32 accumulate):
//   hout[v] = 0.9 * sum_e w[e]*hin[col[e]] + 0.1*x0[v]
// warp per node; lane handles 4 features (8B half load). Writes half normally,
// fp32 on the final step (hout_f != nullptr).
// ---------------------------------------------------------------------------
__global__ void k_prop(const uint2* __restrict__ hin, const float* __restrict__ x0,
                       uint2* __restrict__ hout_h, float* __restrict__ hout_f) {
    int gw = (blockIdx.x * blockDim.x + threadIdx.x) >> 5;
    int lane = threadIdx.x & 31;
    if (gw >= NN) return;

    int beg = g_rowptr[gw];
    int end = g_rowptr[gw + 1];

    float ax = 0.f, ay = 0.f, az = 0.f, aw = 0.f;
    int e = beg;
    for (; e + 4 <= end; e += 4) {
        uint2 m0 = g_meta[e],     m1 = g_meta[e + 1];
        uint2 m2 = g_meta[e + 2], m3 = g_meta[e + 3];
        uint2 u0 = hin[(size_t)m0.x * 32 + lane];
        uint2 u1 = hin[(size_t)m1.x * 32 + lane];
        uint2 u2 = hin[(size_t)m2.x * 32 + lane];
        uint2 u3 = hin[(size_t)m3.x * 32 + lane];
        float w0 = __uint_as_float(m0.y), w1 = __uint_as_float(m1.y);
        float w2 = __uint_as_float(m2.y), w3 = __uint_as_float(m3.y);

        float2 a0 = __half22float2(*reinterpret_cast<__half2*>(&u0.x));
        float2 b0 = __half22float2(*reinterpret_cast<__half2*>(&u0.y));
        float2 a1 = __half22float2(*reinterpret_cast<__half2*>(&u1.x));
        float2 b1 = __half22float2(*reinterpret_cast<__half2*>(&u1.y));
        float2 a2 = __half22float2(*reinterpret_cast<__half2*>(&u2.x));
        float2 b2 = __half22float2(*reinterpret_cast<__half2*>(&u2.y));
        float2 a3 = __half22float2(*reinterpret_cast<__half2*>(&u3.x));
        float2 b3 = __half22float2(*reinterpret_cast<__half2*>(&u3.y));

        ax += w0 * a0.x + w1 * a1.x + w2 * a2.x + w3 * a3.x;
        ay += w0 * a0.y + w1 * a1.y + w2 * a2.y + w3 * a3.y;
        az += w0 * b0.x + w1 * b1.x + w2 * b2.x + w3 * b3.x;
        aw += w0 * b0.y + w1 * b1.y + w2 * b2.y + w3 * b3.y;
    }
    for (; e < end; e++) {
        uint2 m = g_meta[e];
        float w = __uint_as_float(m.y);
        uint2 u = hin[(size_t)m.x * 32 + lane];
        float2 a = __half22float2(*reinterpret_cast<__half2*>(&u.x));
        float2 b = __half22float2(*reinterpret_cast<__half2*>(&u.y));
        ax += w * a.x; ay += w * a.y; az += w * b.x; aw += w * b.y;
    }

    float4 xv = *(const float4*)(x0 + (size_t)gw * 128 + lane * 4);
    float r0 = (1.0f - ALPHA) * ax + ALPHA * xv.x;
    float r1 = (1.0f - ALPHA) * ay + ALPHA * xv.y;
    float r2 = (1.0f - ALPHA) * az + ALPHA * xv.z;
    float r3 = (1.0f - ALPHA) * aw + ALPHA * xv.w;

    if (hout_f) {
        float4 o = make_float4(r0, r1, r2, r3);
        *(float4*)(hout_f + (size_t)gw * 128 + lane * 4) = o;
    } else {
        __half2 o0 = __floats2half2_rn(r0, r1);
        __half2 o1 = __floats2half2_rn(r2, r3);
        uint2 o;
        o.x = *reinterpret_cast<unsigned*>(&o0);
        o.y = *reinterpret_cast<unsigned*>(&o1);
        hout_h[(size_t)gw * 32 + lane] = o;
    }
}

// ---------------------------------------------------------------------------
// Link layer: warp per pair (fp32 features).
// ---------------------------------------------------------------------------
__global__ void k_link(const float* __restrict__ h, const int* __restrict__ idx,
                       const float* __restrict__ W3, const float* __restrict__ b3,
                       float* __restrict__ out) {
    int gw = (blockIdx.x * blockDim.x + threadIdx.x) >> 5;
    int lane = threadIdx.x & 31;
    if (gw >= PP) return;

    float4 w00 = *(const float4*)(W3 + 4 * lane);
    float4 w01 = *(const float4*)(W3 + 128 + 4 * lane);
    float4 w10 = *(const float4*)(W3 + 256 + 4 * lane);
    float4 w11 = *(const float4*)(W3 + 256 + 128 + 4 * lane);

    int i0 = idx[2 * gw];
    int i1 = idx[2 * gw + 1];
    float4 a = *(const float4*)(h + (size_t)i0 * 128 + lane * 4);
    float4 b = *(const float4*)(h + (size_t)i1 * 128 + lane * 4);
    a.x = fmaxf(a.x, 0.f); a.y = fmaxf(a.y, 0.f);
    a.z = fmaxf(a.z, 0.f); a.w = fmaxf(a.w, 0.f);
    b.x = fmaxf(b.x, 0.f); b.y = fmaxf(b.y, 0.f);
    b.z = fmaxf(b.z, 0.f); b.w = fmaxf(b.w, 0.f);

    float l0 = a.x * w00.x + a.y * w00.y + a.z * w00.z + a.w * w00.w
             + b.x * w01.x + b.y * w01.y + b.z * w01.z + b.w * w01.w;
    float l1 = a.x * w10.x + a.y * w10.y + a.z * w10.z + a.w * w10.w
             + b.x * w11.x + b.y * w11.y + b.z * w11.z + b.w * w11.w;

#pragma unroll
    for (int off = 16; off; off >>= 1) {
        l0 += __shfl_xor_sync(0xffffffffu, l0, off);
        l1 += __shfl_xor_sync(0xffffffffu, l1, off);
    }
    if (lane == 0) {
        l0 += b3[0];
        l1 += b3[1];
        float m = fmaxf(l0, l1);
        float lse = m + logf(expf(l0 - m) + expf(l1 - m));
        out[2 * gw]     = l0 - lse;
        out[2 * gw + 1] = l1 - lse;
    }
}

// ---------------------------------------------------------------------------
// Launch
// ---------------------------------------------------------------------------
extern "C" void kernel_launch(void* const* d_in, const int* in_sizes, int n_in,
                              void* d_out, int out_size) {
    const float* x     = (const float*)d_in[0];
    const int*   ei    = (const int*)d_in[1];
    const int*   index = (const int*)d_in[2];
    const float* W1    = (const float*)d_in[3];
    const float* b1    = (const float*)d_in[4];
    const float* W2    = (const float*)d_in[5];
    const float* b2    = (const float*)d_in[6];
    const float* W3    = (const float*)d_in[7];
    const float* b3    = (const float*)d_in[8];
    float* out = (float*)d_out;

    float *Hf, *Hg;
    uint2 *H1, *H2;
    cudaGetSymbolAddress((void**)&Hf, g_Hf);
    cudaGetSymbolAddress((void**)&Hg, g_Hg);
    cudaGetSymbolAddress((void**)&H1, g_h1);
    cudaGetSymbolAddress((void**)&H2, g_h2);

    const int gemm_smem = (128 * 128 + 128 * 8) * (int)sizeof(float);  // 69632
    cudaFuncSetAttribute(k_gemm, cudaFuncAttributeMaxDynamicSharedMemorySize,
                         gemm_smem);

    // ---- graph normalization / CSR build ----
    k_init<<<(NN + 255) / 256, 256>>>();
    k_hist<<<(EG + 255) / 256, 256>>>(ei);
    k_scan<<<1, 1024>>>();
    k_prep<<<(NN + 255) / 256, 256>>>();
    k_fill<<<(EE + 255) / 256, 256>>>(ei);

    const int prop_blocks = (NN * 32 + 255) / 256;   // 6250
    const int gemm_blocks = 444;

    // ---- layer 1: Hf = x @ W1^T + b1 (fp32 + fp16); 10x APPNP ----
    k_gemm<<<gemm_blocks, 128, gemm_smem>>>(x, W1, b1, Hf, (__half*)H1, 0);
    {
        uint2* bufs[2] = {H2, H1};
        const uint2* cur = H1;
        for (int k = 0; k < 9; k++) {
            uint2* o = bufs[k & 1];
            k_prop<<<prop_blocks, 256>>>(cur, Hf, o, nullptr);
            cur = o;
        }
        // after 9 steps cur == H2; final step -> fp32 Hg
        k_prop<<<prop_blocks, 256>>>(cur, Hf, nullptr, Hg);
    }

    // ---- layer 2: Hf = relu(Hg) @ W2^T + b2 ; 10x APPNP ----
    k_gemm<<<gemm_blocks, 128, gemm_smem>>>(Hg, W2, b2, Hf, (__half*)H1, 1);
    {
        uint2* bufs[2] = {H2, H1};
        const uint2* cur = H1;
        for (int k = 0; k < 9; k++) {
            uint2* o = bufs[k & 1];
            k_prop<<<prop_blocks, 256>>>(cur, Hf, o, nullptr);
            cur = o;
        }
        k_prop<<<prop_blocks, 256>>>(cur, Hf, nullptr, Hg);
    }

    // ---- link prediction head ----
    k_link<<<(PP * 32 + 255) / 256, 256>>>(Hg, index, W3, b3, out);
}